// round 12
// baseline (speedup 1.0000x reference)
#include <cuda_runtime.h>
#include <cuda_fp16.h>
#include <math.h>

#define BB  16
#define NPT 1024
#define EPSW 1e-5f
#define L2E 1.4426950408889634f
#define NJC 8                      // j-chunks for col partials

typedef unsigned long long ull;

// ---------------- scratch (static device globals; no allocations) ----------------
static __device__ __half g_Eh[BB][NPT][NPT];     // exp(affinity) fp16, 32MB, pinned L2 via evict_last policy
static __device__ float  g_part[NJC][BB][NPT];   // column-pass partial sums (8 j-chunks)
static __device__ float  g_refSoA[BB][6][NPT];
static __device__ float  g_gn[BB][NPT];
static __device__ float  g_featS[BB][6][NPT];
static __device__ float  g_fn[BB][NPT];
static __device__ float  g_eu[BB][NPT];          // exp(-u_j)
static __device__ float  g_w[BB][NPT];
static __device__ float  g_wrx[BB][NPT];
static __device__ float  g_wry[BB][NPT];
static __device__ float  g_wrz[BB][NPT];
static __device__ double g_T[BB][12];

__device__ __forceinline__ float fast_ex2(float x){ float y; asm("ex2.approx.ftz.f32 %0, %1;" : "=f"(y) : "f"(x)); return y; }
__device__ __forceinline__ int dval(const int* p, int d){ return p ? __ldg(p) : d; }

// L2 evict-last policy (createpolicy + cache_hint works at any access width on sm_103)
__device__ __forceinline__ ull evl_policy(){
    ull pol;
    asm("createpolicy.fractional.L2::evict_last.b64 %0, 1.0;" : "=l"(pol));
    return pol;
}
__device__ __forceinline__ uint4 ldg_evl(const void* p, ull pol){
    uint4 v;
    asm volatile("ld.global.nc.L2::cache_hint.v4.u32 {%0,%1,%2,%3}, [%4], %5;"
                 : "=r"(v.x), "=r"(v.y), "=r"(v.z), "=r"(v.w) : "l"(p), "l"(pol));
    return v;
}
__device__ __forceinline__ void stg_evl32(void* p, unsigned v, ull pol){
    asm volatile("st.global.L2::cache_hint.u32 [%0], %1, %2;" :: "l"(p), "r"(v), "l"(pol) : "memory");
}

// packed f32x2 helpers (Blackwell FFMA2)
__device__ __forceinline__ ull pack2(float lo, float hi){ ull r; asm("mov.b64 %0, {%1, %2};" : "=l"(r) : "f"(lo), "f"(hi)); return r; }
__device__ __forceinline__ void unpack2(ull v, float& lo, float& hi){ asm("mov.b64 {%0, %1}, %2;" : "=f"(lo), "=f"(hi) : "l"(v)); }
__device__ __forceinline__ ull fma2(ull a, ull b, ull c){ ull d; asm("fma.rn.f32x2 %0, %1, %2, %3;" : "=l"(d) : "l"(a), "l"(b), "l"(c)); return d; }
__device__ __forceinline__ ull add2(ull a, ull b){ ull d; asm("add.rn.f32x2 %0, %1, %2;" : "=l"(d) : "l"(a), "l"(b)); return d; }

// ---------------- init ----------------
__global__ void k_init(const float* __restrict__ ref)
{
    int idx = blockIdx.x * 256 + threadIdx.x;
    if (idx < BB * NPT) {
        int b = idx >> 10, k = idx & 1023;
        const float* p = ref + (size_t)idx * 6;
        float n = 0.f;
#pragma unroll
        for (int c = 0; c < 6; c++) { float x = p[c]; g_refSoA[b][c][k] = x; n += x * x; }
        g_gn[b][k] = n;
    }
    if (idx < BB) {
        double* T = g_T[idx];
#pragma unroll
        for (int m = 0; m < 3; m++)
#pragma unroll
            for (int c = 0; c < 4; c++) T[m * 4 + c] = (m == c) ? 1.0 : 0.0;
    }
}

// ---------------- prep ----------------
__global__ void k_prep(const int* nreg, int r, const float* __restrict__ src)
{
    if (r >= dval(nreg, 3)) return;
    int idx = blockIdx.x * 256 + threadIdx.x;
    if (idx >= BB * NPT) return;
    int b = idx >> 10, j = idx & 1023;
    const double* T = g_T[b];
    const float* p = src + (size_t)idx * 6;
    float x = p[0], y = p[1], z = p[2], n3 = p[3], n4 = p[4], n5 = p[5];
    float q0 = (float)(T[0] * x + T[1] * y + T[2]  * z + T[3]);
    float q1 = (float)(T[4] * x + T[5] * y + T[6]  * z + T[7]);
    float q2 = (float)(T[8] * x + T[9] * y + T[10] * z + T[11]);
    g_featS[b][0][j] = q0; g_featS[b][1][j] = q1; g_featS[b][2][j] = q2;
    g_featS[b][3][j] = n3; g_featS[b][4][j] = n4; g_featS[b][5][j] = n5;
    g_fn[b][j] = q0*q0 + q1*q1 + q2*q2 + n3*n3 + n4*n4 + n5*n5;
}

// ---------------- mat: E = exp(a) (fp16) via f32x2, fused first row pass (ev==1) ----------------
__global__ void __launch_bounds__(256) k_mat(const int* nreg, int r,
                                             const float* __restrict__ beta_, const float* __restrict__ alpha_)
{
    if (r >= dval(nreg, 3)) return;
    int b = blockIdx.y;
    __shared__ float gs[6][NPT];
    __shared__ float pk[NPT];
    float bl = beta_[b] * L2E;
    for (int i = threadIdx.x; i < NPT; i += 256) {
#pragma unroll
        for (int c = 0; c < 6; c++) gs[c][i] = g_refSoA[b][c][i];
        pk[i] = bl * g_gn[b][i];
    }
    __syncthreads();
    ull pol = evl_policy();
    int warp = threadIdx.x >> 5, lane = threadIdx.x & 31;
    int j0 = blockIdx.x * 32 + warp * 4;
    float al = alpha_[b];
    ull wj2[4][6], cj2[4];
#pragma unroll
    for (int t = 0; t < 4; t++) {
        int j = j0 + t;
#pragma unroll
        for (int c = 0; c < 6; c++) { float w = 2.f * bl * g_featS[b][c][j]; wj2[t][c] = pack2(w, w); }
        float cj = bl * (al - g_fn[b][j]);
        cj2[t] = pack2(cj, cj);
    }
    __half2* E0 = (__half2*)&g_Eh[b][j0][0];
    float acc[4] = {0.f, 0.f, 0.f, 0.f};
#pragma unroll 2
    for (int i = 0; i < 16; i++) {
        int kk = i * 32 + lane;
        ull g2[6];
#pragma unroll
        for (int c = 0; c < 6; c++) {
            float2 G = ((const float2*)&gs[c][0])[kk];
            g2[c] = pack2(G.x, G.y);
        }
        float2 P = ((const float2*)pk)[kk];
        ull pn = pack2(-P.x, -P.y);
#pragma unroll
        for (int t = 0; t < 4; t++) {
            ull a = add2(cj2[t], pn);
#pragma unroll
            for (int c = 0; c < 6; c++) a = fma2(wj2[t][c], g2[c], a);
            float ax, ay; unpack2(a, ax, ay);
            float e0 = fast_ex2(ax), e1 = fast_ex2(ay);
            __half2 h = __floats2half2_rn(e0, e1);
            stg_evl32(&E0[t * (NPT / 2) + kk], *(const unsigned*)&h, pol);
            acc[t] += e0 + e1;
        }
    }
#pragma unroll
    for (int t = 0; t < 4; t++)
#pragma unroll
        for (int o = 16; o; o >>= 1) acc[t] += __shfl_xor_sync(0xffffffffu, acc[t], o);
    if (lane == 0) {
#pragma unroll
        for (int t = 0; t < 4; t++) g_eu[b][j0 + t] = 1.f / (1.f + acc[t]);
    }
}

// ---------------- col pass (partial): part[jc][b][k] = sum_{j in 128-row chunk} E_jk * eu_j ----------------
// grid (64, BB): kc = x&7 (8 chunks of 128 cols), jc = x>>3 (8 chunks of 128 rows)
__global__ void __launch_bounds__(256) k_colp(const int* nreg, const int* nsk, int r, int s)
{
    if (r >= dval(nreg, 3) || s >= dval(nsk, 5)) return;
    int b  = blockIdx.y;
    int kc = blockIdx.x & 7;
    int jc = blockIdx.x >> 3;
    int t = threadIdx.x;
    int col8 = t & 15;          // 16 groups of 8 columns
    int rg   = t >> 4;          // 16 row-chunks of 8 rows
    __shared__ float eus[128];
    __shared__ float red[16][128];
    if (t < 128) eus[t] = g_eu[b][jc * 128 + t];
    __syncthreads();
    ull pol = evl_policy();
    const char* Ebase = (const char*)(&g_Eh[b][jc * 128 + rg * 8][kc * 128 + col8 * 8]);
    const size_t rowB = NPT * 2;
    float a0=0,a1=0,a2=0,a3=0,a4=0,a5=0,a6=0,a7=0;
#pragma unroll
    for (int jj = 0; jj < 8; jj++) {
        uint4 v = ldg_evl(Ebase + (size_t)jj * rowB, pol);
        float e = eus[rg * 8 + jj];
        float2 p0 = __half22float2(*(const __half2*)&v.x);
        float2 p1 = __half22float2(*(const __half2*)&v.y);
        float2 p2 = __half22float2(*(const __half2*)&v.z);
        float2 p3 = __half22float2(*(const __half2*)&v.w);
        a0 = fmaf(p0.x, e, a0); a1 = fmaf(p0.y, e, a1);
        a2 = fmaf(p1.x, e, a2); a3 = fmaf(p1.y, e, a3);
        a4 = fmaf(p2.x, e, a4); a5 = fmaf(p2.y, e, a5);
        a6 = fmaf(p3.x, e, a6); a7 = fmaf(p3.y, e, a7);
    }
    red[rg][0*16 + col8] = a0; red[rg][1*16 + col8] = a1;
    red[rg][2*16 + col8] = a2; red[rg][3*16 + col8] = a3;
    red[rg][4*16 + col8] = a4; red[rg][5*16 + col8] = a5;
    red[rg][6*16 + col8] = a6; red[rg][7*16 + col8] = a7;
    __syncthreads();
    if (t < 128) {
        int c8 = t >> 3, ci = t & 7;       // column c = c8*8 + ci
        float s4 = 0.f;
#pragma unroll
        for (int rr = 0; rr < 16; rr++) s4 += red[rr][ci * 16 + c8];
        g_part[jc][b][kc * 128 + c8 * 8 + ci] = s4;
    }
}

// ---------------- row pass: eu_j = 1/(1 + sum_k E_jk * ev_k), ev folded from 8 partials ----------------
// grid (64, BB): 8 warps/block, 2 rows/warp
__global__ void __launch_bounds__(256) k_rowp(const int* nreg, const int* nsk, int r, int s)
{
    if (r >= dval(nreg, 3) || s >= dval(nsk, 5)) return;
    int b = blockIdx.y;
    __shared__ float evs[NPT];
    for (int i = threadIdx.x; i < NPT; i += 256) {
        float sum = 0.f;
#pragma unroll
        for (int jc = 0; jc < NJC; jc++) sum += g_part[jc][b][i];
        evs[i] = 1.f / (1.f + sum);
    }
    __syncthreads();
    ull pol = evl_policy();
    int w = threadIdx.x >> 5, lane = threadIdx.x & 31;
    int j0 = (blockIdx.x * 8 + w) * 2;
    float acc0 = 0.f, acc1 = 0.f;
#pragma unroll
    for (int i = 0; i < 4; i++) {
        int k0 = i * 256 + lane * 8;
        float2 e0 = *(const float2*)&evs[k0];
        float2 e1 = *(const float2*)&evs[k0 + 2];
        float2 e2 = *(const float2*)&evs[k0 + 4];
        float2 e3 = *(const float2*)&evs[k0 + 6];
        uint4 v0 = ldg_evl(&g_Eh[b][j0 + 0][k0], pol);
        uint4 v1 = ldg_evl(&g_Eh[b][j0 + 1][k0], pol);
        {
            float2 p0 = __half22float2(*(const __half2*)&v0.x), p1 = __half22float2(*(const __half2*)&v0.y);
            float2 p2 = __half22float2(*(const __half2*)&v0.z), p3 = __half22float2(*(const __half2*)&v0.w);
            acc0 = fmaf(p0.x, e0.x, fmaf(p0.y, e0.y, acc0));
            acc0 = fmaf(p1.x, e1.x, fmaf(p1.y, e1.y, acc0));
            acc0 = fmaf(p2.x, e2.x, fmaf(p2.y, e2.y, acc0));
            acc0 = fmaf(p3.x, e3.x, fmaf(p3.y, e3.y, acc0));
        }
        {
            float2 p0 = __half22float2(*(const __half2*)&v1.x), p1 = __half22float2(*(const __half2*)&v1.y);
            float2 p2 = __half22float2(*(const __half2*)&v1.z), p3 = __half22float2(*(const __half2*)&v1.w);
            acc1 = fmaf(p0.x, e0.x, fmaf(p0.y, e0.y, acc1));
            acc1 = fmaf(p1.x, e1.x, fmaf(p1.y, e1.y, acc1));
            acc1 = fmaf(p2.x, e2.x, fmaf(p2.y, e2.y, acc1));
            acc1 = fmaf(p3.x, e3.x, fmaf(p3.y, e3.y, acc1));
        }
    }
#pragma unroll
    for (int o = 16; o; o >>= 1) {
        acc0 += __shfl_xor_sync(0xffffffffu, acc0, o);
        acc1 += __shfl_xor_sync(0xffffffffu, acc1, o);
    }
    if (lane == 0) {
        g_eu[b][j0 + 0] = 1.f / (1.f + acc0);
        g_eu[b][j0 + 1] = 1.f / (1.f + acc1);
    }
}

// ---------------- consume: exact fp32 recompute of E; row sums, perm @ ref_xyz, perm write ----------------
__global__ void __launch_bounds__(256) k_consume(const int* nreg, int r,
                                                 const float* __restrict__ beta_, const float* __restrict__ alpha_,
                                                 float* __restrict__ perm_out)
{
    int nr = dval(nreg, 3);
    if (r >= nr) return;
    bool last = (r == nr - 1);
    int b = blockIdx.y;
    __shared__ float gs[6][NPT];
    __shared__ float pk[NPT];
    __shared__ float evs[NPT];
    float bl = beta_[b] * L2E;
    for (int i = threadIdx.x; i < NPT; i += 256) {
#pragma unroll
        for (int c = 0; c < 6; c++) gs[c][i] = g_refSoA[b][c][i];
        pk[i] = bl * g_gn[b][i];
        float sum = 0.f;
#pragma unroll
        for (int jc = 0; jc < NJC; jc++) sum += g_part[jc][b][i];
        evs[i] = 1.f / (1.f + sum);
    }
    __syncthreads();
    int warp = threadIdx.x >> 5, lane = threadIdx.x & 31;
    int j0 = blockIdx.x * 32 + warp * 4;
    float al = alpha_[b];
    float wj[4][6], cj[4], eu[4];
#pragma unroll
    for (int t = 0; t < 4; t++) {
        int j = j0 + t;
#pragma unroll
        for (int c = 0; c < 6; c++) wj[t][c] = 2.f * bl * g_featS[b][c][j];
        cj[t] = bl * (al - g_fn[b][j]);
        eu[t] = g_eu[b][j];
    }
    float S[4] = {0,0,0,0}, SX[4] = {0,0,0,0}, SY[4] = {0,0,0,0}, SZ[4] = {0,0,0,0};
    if (last) {
        float* pb[4];
#pragma unroll
        for (int t = 0; t < 4; t++) pb[t] = perm_out + ((size_t)(b * NPT + j0 + t)) * NPT;
#pragma unroll 2
        for (int i = 0; i < 32; i++) {
            int k = i * 32 + lane;
            float G[6];
#pragma unroll
            for (int c = 0; c < 6; c++) G[c] = gs[c][k];
            float P = pk[k], ev = evs[k];
#pragma unroll
            for (int t = 0; t < 4; t++) {
                float a = cj[t] - P;
#pragma unroll
                for (int c = 0; c < 6; c++) a = fmaf(wj[t][c], G[c], a);
                float e = fast_ex2(a) * ev;
                S[t] += e;
                SX[t] = fmaf(e, G[0], SX[t]);
                SY[t] = fmaf(e, G[1], SY[t]);
                SZ[t] = fmaf(e, G[2], SZ[t]);
                pb[t][k] = e * eu[t];
            }
        }
    } else {
#pragma unroll 2
        for (int i = 0; i < 32; i++) {
            int k = i * 32 + lane;
            float G[6];
#pragma unroll
            for (int c = 0; c < 6; c++) G[c] = gs[c][k];
            float P = pk[k], ev = evs[k];
#pragma unroll
            for (int t = 0; t < 4; t++) {
                float a = cj[t] - P;
#pragma unroll
                for (int c = 0; c < 6; c++) a = fmaf(wj[t][c], G[c], a);
                float e = fast_ex2(a) * ev;
                S[t] += e;
                SX[t] = fmaf(e, G[0], SX[t]);
                SY[t] = fmaf(e, G[1], SY[t]);
                SZ[t] = fmaf(e, G[2], SZ[t]);
            }
        }
    }
#pragma unroll
    for (int t = 0; t < 4; t++) {
#pragma unroll
        for (int o = 16; o; o >>= 1) {
            S[t]  += __shfl_xor_sync(0xffffffffu, S[t],  o);
            SX[t] += __shfl_xor_sync(0xffffffffu, SX[t], o);
            SY[t] += __shfl_xor_sync(0xffffffffu, SY[t], o);
            SZ[t] += __shfl_xor_sync(0xffffffffu, SZ[t], o);
        }
    }
    if (lane == 0) {
#pragma unroll
        for (int t = 0; t < 4; t++) {
            int j = j0 + t;
            float W = S[t] * eu[t];
            g_w[b][j] = W;
            float inv = 1.f / (W + EPSW);
            g_wrx[b][j] = SX[t] * eu[t] * inv;
            g_wry[b][j] = SY[t] * eu[t] * inv;
            g_wrz[b][j] = SZ[t] * eu[t] * inv;
        }
    }
}

// ---------------- fit: weighted Kabsch (fp64 Jacobi SVD) + compose transform ----------------
__global__ void __launch_bounds__(256) k_fit(const int* nreg, int r, float* __restrict__ T_out)
{
    int nr = dval(nreg, 3);
    if (r >= nr) return;
    int b = blockIdx.x;
    int lane = threadIdx.x & 31, warp = threadIdx.x >> 5;
    __shared__ double sred[8][9];
    __shared__ double sc[8];

    double acc[7] = {0,0,0,0,0,0,0};
    for (int j = threadIdx.x; j < NPT; j += 256) {
        double w  = g_w[b][j];
        double ax = g_featS[b][0][j], ay = g_featS[b][1][j], az = g_featS[b][2][j];
        double bx = g_wrx[b][j], by = g_wry[b][j], bz = g_wrz[b][j];
        acc[0] += w;
        acc[1] += w*ax; acc[2] += w*ay; acc[3] += w*az;
        acc[4] += w*bx; acc[5] += w*by; acc[6] += w*bz;
    }
#pragma unroll
    for (int i = 0; i < 7; i++)
#pragma unroll
        for (int o = 16; o; o >>= 1) acc[i] += __shfl_xor_sync(0xffffffffu, acc[i], o);
    if (lane == 0)
#pragma unroll
        for (int i = 0; i < 7; i++) sred[warp][i] = acc[i];
    __syncthreads();
    if (threadIdx.x == 0) {
        double tot[7] = {0,0,0,0,0,0,0};
        for (int w = 0; w < 8; w++)
            for (int i = 0; i < 7; i++) tot[i] += sred[w][i];
        double den = tot[0] + 1e-5;
        sc[0] = den;
        for (int i = 0; i < 6; i++) sc[1 + i] = tot[1 + i] / den;
    }
    __syncthreads();
    double den = sc[0];
    double ca0 = sc[1], ca1 = sc[2], ca2 = sc[3];
    double cb0 = sc[4], cb1 = sc[5], cb2 = sc[6];

    double cv[9] = {0,0,0,0,0,0,0,0,0};
    for (int j = threadIdx.x; j < NPT; j += 256) {
        double wn = (double)g_w[b][j] / den;
        double ax = g_featS[b][0][j] - ca0, ay = g_featS[b][1][j] - ca1, az = g_featS[b][2][j] - ca2;
        double bx = g_wrx[b][j] - cb0, by = g_wry[b][j] - cb1, bz = g_wrz[b][j] - cb2;
        cv[0] += wn*ax*bx; cv[1] += wn*ax*by; cv[2] += wn*ax*bz;
        cv[3] += wn*ay*bx; cv[4] += wn*ay*by; cv[5] += wn*ay*bz;
        cv[6] += wn*az*bx; cv[7] += wn*az*by; cv[8] += wn*az*bz;
    }
#pragma unroll
    for (int i = 0; i < 9; i++)
#pragma unroll
        for (int o = 16; o; o >>= 1) cv[i] += __shfl_xor_sync(0xffffffffu, cv[i], o);
    if (lane == 0)
#pragma unroll
        for (int i = 0; i < 9; i++) sred[warp][i] = cv[i];
    __syncthreads();

    if (threadIdx.x == 0) {
        double C[3][3];
        {
            double tot[9] = {0,0,0,0,0,0,0,0,0};
            for (int w = 0; w < 8; w++)
                for (int i = 0; i < 9; i++) tot[i] += sred[w][i];
            for (int m = 0; m < 3; m++)
                for (int n = 0; n < 3; n++) C[m][n] = tot[m * 3 + n];
        }
        double A[3][3];
        for (int i = 0; i < 3; i++)
            for (int j = 0; j < 3; j++)
                A[i][j] = C[0][i]*C[0][j] + C[1][i]*C[1][j] + C[2][i]*C[2][j];
        double V[3][3] = {{1,0,0},{0,1,0},{0,0,1}};
        const int PP[3] = {0,0,1}, QQ[3] = {1,2,2};
        for (int sweep = 0; sweep < 30; sweep++) {
            double off = A[0][1]*A[0][1] + A[0][2]*A[0][2] + A[1][2]*A[1][2];
            if (off < 1e-26) break;
            for (int pi = 0; pi < 3; pi++) {
                int p = PP[pi], q = QQ[pi];
                double apq = A[p][q];
                if (fabs(apq) < 1e-300) continue;
                double theta = (A[q][q] - A[p][p]) / (2.0 * apq);
                double tt = ((theta >= 0.0) ? 1.0 : -1.0) / (fabs(theta) + sqrt(theta*theta + 1.0));
                double c = 1.0 / sqrt(tt*tt + 1.0), sn = tt * c;
                int m = 3 - p - q;
                double amp = A[m][p], amq = A[m][q];
                double app = A[p][p], aqq = A[q][q];
                A[p][p] = app - tt * apq;
                A[q][q] = aqq + tt * apq;
                A[p][q] = A[q][p] = 0.0;
                A[m][p] = A[p][m] = c*amp - sn*amq;
                A[m][q] = A[q][m] = sn*amp + c*amq;
                for (int mm = 0; mm < 3; mm++) {
                    double vp = V[mm][p], vq = V[mm][q];
                    V[mm][p] = c*vp - sn*vq;
                    V[mm][q] = sn*vp + c*vq;
                }
            }
        }
        double lam[3] = {A[0][0], A[1][1], A[2][2]};
        for (int i = 0; i < 2; i++)
            for (int j = i + 1; j < 3; j++)
                if (lam[j] > lam[i]) {
                    double tl = lam[i]; lam[i] = lam[j]; lam[j] = tl;
                    for (int m = 0; m < 3; m++) { double tv = V[m][i]; V[m][i] = V[m][j]; V[m][j] = tv; }
                }
        double v0[3] = {V[0][0], V[1][0], V[2][0]};
        double v1[3] = {V[0][1], V[1][1], V[2][1]};
        double v2[3] = {V[0][2], V[1][2], V[2][2]};
        double u0[3], u1[3], u2[3];
        for (int m = 0; m < 3; m++) {
            u0[m] = C[m][0]*v0[0] + C[m][1]*v0[1] + C[m][2]*v0[2];
            u1[m] = C[m][0]*v1[0] + C[m][1]*v1[1] + C[m][2]*v1[2];
            u2[m] = C[m][0]*v2[0] + C[m][1]*v2[1] + C[m][2]*v2[2];
        }
        double n0 = sqrt(u0[0]*u0[0] + u0[1]*u0[1] + u0[2]*u0[2]);
        if (n0 > 1e-150) { u0[0] /= n0; u0[1] /= n0; u0[2] /= n0; }
        else { u0[0] = 1; u0[1] = 0; u0[2] = 0; n0 = 0; }
        double d01 = u0[0]*u1[0] + u0[1]*u1[1] + u0[2]*u1[2];
        for (int m = 0; m < 3; m++) u1[m] -= d01 * u0[m];
        double n1 = sqrt(u1[0]*u1[0] + u1[1]*u1[1] + u1[2]*u1[2]);
        if (n1 > 1e-150) { u1[0] /= n1; u1[1] /= n1; u1[2] /= n1; }
        else {
            double e[3] = {0,0,0};
            e[(fabs(u0[0]) < 0.9) ? 0 : 1] = 1.0;
            double de = u0[0]*e[0] + u0[1]*e[1] + u0[2]*e[2];
            for (int m = 0; m < 3; m++) u1[m] = e[m] - de * u0[m];
            double nn = sqrt(u1[0]*u1[0] + u1[1]*u1[1] + u1[2]*u1[2]);
            for (int m = 0; m < 3; m++) u1[m] /= nn;
        }
        double d02 = u0[0]*u2[0] + u0[1]*u2[1] + u0[2]*u2[2];
        double d12 = u1[0]*u2[0] + u1[1]*u2[1] + u1[2]*u2[2];
        for (int m = 0; m < 3; m++) u2[m] -= d02 * u0[m] + d12 * u1[m];
        double n2 = sqrt(u2[0]*u2[0] + u2[1]*u2[1] + u2[2]*u2[2]);
        if (n2 > 1e-12 * (n0 + 1e-300)) { u2[0] /= n2; u2[1] /= n2; u2[2] /= n2; }
        else {
            u2[0] = u0[1]*u1[2] - u0[2]*u1[1];
            u2[1] = u0[2]*u1[0] - u0[0]*u1[2];
            u2[2] = u0[0]*u1[1] - u0[1]*u1[0];
        }
        double cx0 = u1[1]*u2[2] - u1[2]*u2[1];
        double cx1 = u1[2]*u2[0] - u1[0]*u2[2];
        double cx2 = u1[0]*u2[1] - u1[1]*u2[0];
        double detU = u0[0]*cx0 + u0[1]*cx1 + u0[2]*cx2;
        double cy0 = v1[1]*v2[2] - v1[2]*v2[1];
        double cy1 = v1[2]*v2[0] - v1[0]*v2[2];
        double cy2 = v1[0]*v2[1] - v1[1]*v2[0];
        double detV = v0[0]*cy0 + v0[1]*cy1 + v0[2]*cy2;
        double dd = (detU * detV >= 0.0) ? 1.0 : -1.0;
        double R[3][3];
        for (int m = 0; m < 3; m++)
            for (int n = 0; n < 3; n++)
                R[m][n] = v0[m]*u0[n] + v1[m]*u1[n] + dd * v2[m]*u2[n];
        double t3[3];
        t3[0] = cb0 - (R[0][0]*ca0 + R[0][1]*ca1 + R[0][2]*ca2);
        t3[1] = cb1 - (R[1][0]*ca0 + R[1][1]*ca1 + R[1][2]*ca2);
        t3[2] = cb2 - (R[2][0]*ca0 + R[2][1]*ca1 + R[2][2]*ca2);
        double* To = g_T[b];
        double Rn[9], tn[3];
        for (int m = 0; m < 3; m++) {
            for (int n = 0; n < 3; n++)
                Rn[m*3+n] = R[m][0]*To[0*4+n] + R[m][1]*To[1*4+n] + R[m][2]*To[2*4+n];
            tn[m] = R[m][0]*To[3] + R[m][1]*To[7] + R[m][2]*To[11] + t3[m];
        }
        for (int m = 0; m < 3; m++) {
            for (int n = 0; n < 3; n++) To[m*4+n] = Rn[m*3+n];
            To[m*4+3] = tn[m];
        }
        if (r == nr - 1 && T_out) {
            for (int m = 0; m < 3; m++)
                for (int n = 0; n < 4; n++)
                    T_out[b * 12 + m * 4 + n] = (float)To[m * 4 + n];
        }
    }
}

// ---------------- launch ----------------
extern "C" void kernel_launch(void* const* d_in, const int* in_sizes, int n_in,
                              void* d_out, int out_size)
{
    const float* src   = (const float*)d_in[0];
    const float* ref   = (const float*)d_in[1];
    const float* beta  = (const float*)d_in[2];
    const float* alpha = (const float*)d_in[3];
    const int*   nreg  = (n_in > 4) ? (const int*)d_in[4] : nullptr;
    const int*   nsk   = (n_in > 5) ? (const int*)d_in[5] : nullptr;

    float* out = (float*)d_out;
    const long permN = (long)BB * NPT * NPT;
    long off = (long)out_size - permN;
    if (off < 0) off = 0;
    float* perm_out = out + off;
    float* T_out = (off >= BB * 12) ? out : nullptr;

    k_init<<<64, 256>>>(ref);
    const int RMAX = 3, SMAX = 5;
    dim3 gridMat(NPT / 32, BB);     // 512 blocks
    dim3 gridCol(64, BB);           // 8 k-chunks x 8 j-chunks = 1024 blocks
    dim3 gridRow(64, BB);           // 8 warps x 2 rows = 16 rows/block, 1024 blocks
    for (int r = 0; r < RMAX; r++) {
        k_prep<<<64, 256>>>(nreg, r, src);
        k_mat<<<gridMat, 256>>>(nreg, r, beta, alpha);        // writes fp16 E (evict_last) + eu1
        for (int s = 0; s < SMAX; s++) {
            k_colp<<<gridCol, 256>>>(nreg, nsk, r, s);
            if (s < SMAX - 1)
                k_rowp<<<gridRow, 256>>>(nreg, nsk, r, s + 1);
        }
        k_consume<<<gridMat, 256>>>(nreg, r, beta, alpha, perm_out);
        k_fit<<<BB, 256>>>(nreg, r, T_out);
    }
}

// round 13
// speedup vs baseline: 1.0254x; 1.0254x over previous
#include <cuda_runtime.h>
#include <cuda_fp16.h>
#include <math.h>

#define BB  16
#define NPT 1024
#define EPSW 1e-5f
#define L2E 1.4426950408889634f

#define SINK_JC 32     // j-chunks (sink grid.x)
#define SROWS   32     // rows per sink block
#define TR      4      // rows per pipeline tile (8KB)
#define NT      8      // tiles per block
#define NST     4      // pipeline stages

typedef unsigned long long ull;

// ---------------- scratch (static device globals; no allocations) ----------------
static __device__ __half g_Eh[BB][NPT][NPT];        // exp(affinity) fp16, 32MB
static __device__ float  g_part[SINK_JC][BB][NPT];  // col partial sums (2MB)
static __device__ float  g_ev[BB][NPT];             // folded exp(-v_k)
static __device__ float  g_refSoA[BB][6][NPT];
static __device__ float  g_gn[BB][NPT];
static __device__ float  g_featS[BB][6][NPT];
static __device__ float  g_fn[BB][NPT];
static __device__ float  g_eu[BB][NPT];             // exp(-u_j)
static __device__ float  g_w[BB][NPT];
static __device__ float  g_wrx[BB][NPT];
static __device__ float  g_wry[BB][NPT];
static __device__ float  g_wrz[BB][NPT];
static __device__ double g_T[BB][12];

__device__ __forceinline__ float fast_ex2(float x){ float y; asm("ex2.approx.ftz.f32 %0, %1;" : "=f"(y) : "f"(x)); return y; }
__device__ __forceinline__ int dval(const int* p, int d){ return p ? __ldg(p) : d; }
__device__ __forceinline__ unsigned smem_u32(const void* p){
    unsigned a; asm("{ .reg .u64 t; cvta.to.shared.u64 t, %1; cvt.u32.u64 %0, t; }" : "=r"(a) : "l"(p)); return a;
}
__device__ __forceinline__ void mbar_wait(unsigned mb, unsigned ph){
    asm volatile(
        "{\n\t.reg .pred P;\n\t"
        "WL_%=:\n\t"
        "mbarrier.try_wait.parity.acquire.cta.shared::cta.b64 P, [%0], %1, 0x989680;\n\t"
        "@P bra.uni WD_%=;\n\t"
        "bra.uni WL_%=;\n\t"
        "WD_%=:\n\t}"
        :: "r"(mb), "r"(ph) : "memory");
}
__device__ __forceinline__ void bulk_ld(unsigned dst, const void* src, unsigned bytes, unsigned mb){
    asm volatile("mbarrier.arrive.expect_tx.shared.b64 _, [%0], %1;" :: "r"(mb), "r"(bytes) : "memory");
    asm volatile("cp.async.bulk.shared::cta.global.mbarrier::complete_tx::bytes [%0], [%1], %2, [%3];"
                 :: "r"(dst), "l"(src), "r"(bytes), "r"(mb) : "memory");
}

// packed f32x2 helpers (Blackwell FFMA2)
__device__ __forceinline__ ull pack2(float lo, float hi){ ull r; asm("mov.b64 %0, {%1, %2};" : "=l"(r) : "f"(lo), "f"(hi)); return r; }
__device__ __forceinline__ void unpack2(ull v, float& lo, float& hi){ asm("mov.b64 {%0, %1}, %2;" : "=f"(lo), "=f"(hi) : "l"(v)); }
__device__ __forceinline__ ull fma2(ull a, ull b, ull c){ ull d; asm("fma.rn.f32x2 %0, %1, %2, %3;" : "=l"(d) : "l"(a), "l"(b), "l"(c)); return d; }
__device__ __forceinline__ ull add2(ull a, ull b){ ull d; asm("add.rn.f32x2 %0, %1, %2;" : "=l"(d) : "l"(a), "l"(b)); return d; }

// ---------------- init ----------------
__global__ void k_init(const float* __restrict__ ref)
{
    int idx = blockIdx.x * 256 + threadIdx.x;
    if (idx < BB * NPT) {
        int b = idx >> 10, k = idx & 1023;
        const float* p = ref + (size_t)idx * 6;
        float n = 0.f;
#pragma unroll
        for (int c = 0; c < 6; c++) { float x = p[c]; g_refSoA[b][c][k] = x; n += x * x; }
        g_gn[b][k] = n;
    }
    if (idx < BB) {
        double* T = g_T[idx];
#pragma unroll
        for (int m = 0; m < 3; m++)
#pragma unroll
            for (int c = 0; c < 4; c++) T[m * 4 + c] = (m == c) ? 1.0 : 0.0;
    }
}

// ---------------- prep ----------------
__global__ void k_prep(const int* nreg, int r, const float* __restrict__ src)
{
    if (r >= dval(nreg, 3)) return;
    int idx = blockIdx.x * 256 + threadIdx.x;
    if (idx >= BB * NPT) return;
    int b = idx >> 10, j = idx & 1023;
    const double* T = g_T[b];
    const float* p = src + (size_t)idx * 6;
    float x = p[0], y = p[1], z = p[2], n3 = p[3], n4 = p[4], n5 = p[5];
    float q0 = (float)(T[0] * x + T[1] * y + T[2]  * z + T[3]);
    float q1 = (float)(T[4] * x + T[5] * y + T[6]  * z + T[7]);
    float q2 = (float)(T[8] * x + T[9] * y + T[10] * z + T[11]);
    g_featS[b][0][j] = q0; g_featS[b][1][j] = q1; g_featS[b][2][j] = q2;
    g_featS[b][3][j] = n3; g_featS[b][4][j] = n4; g_featS[b][5][j] = n5;
    g_fn[b][j] = q0*q0 + q1*q1 + q2*q2 + n3*n3 + n4*n4 + n5*n5;
}

// ---------------- mat: E = exp(a) (fp16) via f32x2, fused first row pass (ev==1) ----------------
__global__ void __launch_bounds__(256) k_mat(const int* nreg, int r,
                                             const float* __restrict__ beta_, const float* __restrict__ alpha_)
{
    if (r >= dval(nreg, 3)) return;
    int b = blockIdx.y;
    __shared__ float gs[6][NPT];
    __shared__ float pk[NPT];
    float bl = beta_[b] * L2E;
    for (int i = threadIdx.x; i < NPT; i += 256) {
#pragma unroll
        for (int c = 0; c < 6; c++) gs[c][i] = g_refSoA[b][c][i];
        pk[i] = bl * g_gn[b][i];
    }
    __syncthreads();
    int warp = threadIdx.x >> 5, lane = threadIdx.x & 31;
    int j0 = blockIdx.x * 32 + warp * 4;
    float al = alpha_[b];
    ull wj2[4][6], cj2[4];
#pragma unroll
    for (int t = 0; t < 4; t++) {
        int j = j0 + t;
#pragma unroll
        for (int c = 0; c < 6; c++) { float w = 2.f * bl * g_featS[b][c][j]; wj2[t][c] = pack2(w, w); }
        float cj = bl * (al - g_fn[b][j]);
        cj2[t] = pack2(cj, cj);
    }
    __half2* E0 = (__half2*)&g_Eh[b][j0][0];
    float acc[4] = {0.f, 0.f, 0.f, 0.f};
#pragma unroll 2
    for (int i = 0; i < 16; i++) {
        int kk = i * 32 + lane;
        ull g2[6];
#pragma unroll
        for (int c = 0; c < 6; c++) {
            float2 G = ((const float2*)&gs[c][0])[kk];
            g2[c] = pack2(G.x, G.y);
        }
        float2 P = ((const float2*)pk)[kk];
        ull pn = pack2(-P.x, -P.y);
#pragma unroll
        for (int t = 0; t < 4; t++) {
            ull a = add2(cj2[t], pn);
#pragma unroll
            for (int c = 0; c < 6; c++) a = fma2(wj2[t][c], g2[c], a);
            float ax, ay; unpack2(a, ax, ay);
            float e0 = fast_ex2(ax), e1 = fast_ex2(ay);
            E0[t * (NPT / 2) + kk] = __floats2half2_rn(e0, e1);
            acc[t] += e0 + e1;
        }
    }
#pragma unroll
    for (int t = 0; t < 4; t++)
#pragma unroll
        for (int o = 16; o; o >>= 1) acc[t] += __shfl_xor_sync(0xffffffffu, acc[t], o);
    if (lane == 0) {
#pragma unroll
        for (int t = 0; t < 4; t++) g_eu[b][j0 + t] = 1.f / (1.f + acc[t]);
    }
}

// ---------------- sink: ONE TMA-fed E sweep = row update (s>0) + col partials ----------------
// grid (SINK_JC, BB). s==0: partials with g_eu (from mat). s>0: eu' from g_ev, partials with eu'.
__global__ void __launch_bounds__(256) k_sink(const int* nreg, const int* nsk, int r, int s)
{
    if (r >= dval(nreg, 3) || s >= dval(nsk, 5)) return;
    const int b = blockIdx.y, jc = blockIdx.x;
    const int j0 = jc * SROWS;
    const int t = threadIdx.x, w = t >> 5, lane = t & 31;
    const bool first = (s == 0);

    __shared__ __align__(16) __half tile[NST][TR][NPT];   // 32KB
    __shared__ float evs[NPT];                            // 4KB (s>0)
    __shared__ float eusS[SROWS];
    __shared__ float redrow[2][TR][2];                    // double-buffered by tl&1
    __shared__ __align__(8) ull mbar[NST];

    if (t < NST) {
        unsigned mb = smem_u32(&mbar[t]);
        asm volatile("mbarrier.init.shared.b64 [%0], %1;" :: "r"(mb), "r"(1) : "memory");
    }
    __syncthreads();
    asm volatile("fence.proxy.async.shared::cta;" ::: "memory");
    if (t == 0) {
#pragma unroll
        for (int p = 0; p < NST - 1; p++)
            bulk_ld(smem_u32(&tile[p][0][0]), (const void*)&g_Eh[b][j0 + p * TR][0],
                    TR * NPT * 2, smem_u32(&mbar[p]));
    }
    if (first) {
        if (t < SROWS) eusS[t] = g_eu[b][j0 + t];
    } else {
        ((float4*)evs)[t] = ((const float4*)&g_ev[b][0])[t];
    }
    __syncthreads();

    // per-warp ev registers for row phase (fixed k-subset per warp)
    float er[16];
    if (!first) {
        const int h = w & 1;
#pragma unroll
        for (int c = 0; c < 2; c++) {
            float4 f0 = *(const float4*)&evs[h * 512 + c * 256 + lane * 8];
            float4 f1 = *(const float4*)&evs[h * 512 + c * 256 + lane * 8 + 4];
            er[c*8+0]=f0.x; er[c*8+1]=f0.y; er[c*8+2]=f0.z; er[c*8+3]=f0.w;
            er[c*8+4]=f1.x; er[c*8+5]=f1.y; er[c*8+6]=f1.z; er[c*8+7]=f1.w;
        }
    }

    float a0 = 0.f, a1 = 0.f, a2 = 0.f, a3 = 0.f;
    for (int tl = 0; tl < NT; tl++) {
        const int slot = tl & (NST - 1);
        const unsigned ph = (tl >> 2) & 1;
        const int dbuf = tl & 1;
        mbar_wait(smem_u32(&mbar[slot]), ph);
        if (!first) {
            // row phase: 2 warps per row (k-halves)
            const int row = w >> 1, h = w & 1;
            const uint4* rp = (const uint4*)&tile[slot][row][h * 512];
            float sum = 0.f;
#pragma unroll
            for (int c = 0; c < 2; c++) {
                uint4 hv = rp[c * 32 + lane];
                float2 p0 = __half22float2(*(const __half2*)&hv.x);
                float2 p1 = __half22float2(*(const __half2*)&hv.y);
                float2 p2 = __half22float2(*(const __half2*)&hv.z);
                float2 p3 = __half22float2(*(const __half2*)&hv.w);
                const float* e = &er[c * 8];
                sum = fmaf(p0.x, e[0], sum); sum = fmaf(p0.y, e[1], sum);
                sum = fmaf(p1.x, e[2], sum); sum = fmaf(p1.y, e[3], sum);
                sum = fmaf(p2.x, e[4], sum); sum = fmaf(p2.y, e[5], sum);
                sum = fmaf(p3.x, e[6], sum); sum = fmaf(p3.y, e[7], sum);
            }
#pragma unroll
            for (int o = 16; o; o >>= 1) sum += __shfl_xor_sync(0xffffffffu, sum, o);
            if (lane == 0) redrow[dbuf][row][h] = sum;
        }
        __syncthreads();
        // issue tile tl+3 into slot (tl+3)&3 = (tl-1)&3: all threads are past col(tl-1) here
        if (t == 0 && tl + (NST - 1) < NT) {
            int tn = tl + (NST - 1);
            bulk_ld(smem_u32(&tile[tn & (NST - 1)][0][0]),
                    (const void*)&g_Eh[b][j0 + tn * TR][0],
                    TR * NPT * 2, smem_u32(&mbar[tn & (NST - 1)]));
        }
        float et[TR];
        if (first) {
#pragma unroll
            for (int q = 0; q < TR; q++) et[q] = eusS[tl * TR + q];
        } else {
#pragma unroll
            for (int q = 0; q < TR; q++) et[q] = 1.f / (1.f + redrow[dbuf][q][0] + redrow[dbuf][q][1]);
            if (t < TR) eusS[tl * TR + t] = et[t];
        }
        // col phase: thread t -> columns 4t..4t+3 over this tile's rows
#pragma unroll
        for (int q = 0; q < TR; q++) {
            uint2 hv = ((const uint2*)&tile[slot][q][0])[t];
            float2 q0 = __half22float2(*(const __half2*)&hv.x);
            float2 q1 = __half22float2(*(const __half2*)&hv.y);
            a0 = fmaf(q0.x, et[q], a0);
            a1 = fmaf(q0.y, et[q], a1);
            a2 = fmaf(q1.x, et[q], a2);
            a3 = fmaf(q1.y, et[q], a3);
        }
    }
    ((float4*)&g_part[jc][b][0])[t] = make_float4(a0, a1, a2, a3);
    if (!first) {
        __syncthreads();
        if (t < SROWS) g_eu[b][j0 + t] = eusS[t];
    }
}

// ---------------- fold: g_ev[b][k] = 1/(1 + sum_jc part[jc][b][k]) ----------------
// grid (NPT/128, BB) = (8, BB); block: 128 k-values, 8 jc-groups of 4
__global__ void __launch_bounds__(256) k_fold(const int* nreg, const int* nsk, int r, int s)
{
    if (r >= dval(nreg, 3) || s >= dval(nsk, 5)) return;
    int b = blockIdx.y;
    int k0 = blockIdx.x * 128;
    int t = threadIdx.x;
    int kq = t & 31, q = t >> 5;
    float4 s4 = make_float4(0.f, 0.f, 0.f, 0.f);
#pragma unroll
    for (int i = 0; i < 4; i++) {
        float4 v = *(const float4*)&g_part[q * 4 + i][b][k0 + kq * 4];
        s4.x += v.x; s4.y += v.y; s4.z += v.z; s4.w += v.w;
    }
    __shared__ float4 red[8][32];
    red[q][kq] = s4;
    __syncthreads();
    if (t < 32) {
        float4 acc = red[0][t];
#pragma unroll
        for (int qq = 1; qq < 8; qq++) {
            float4 v = red[qq][t];
            acc.x += v.x; acc.y += v.y; acc.z += v.z; acc.w += v.w;
        }
        float4 ev;
        ev.x = 1.f / (1.f + acc.x);
        ev.y = 1.f / (1.f + acc.y);
        ev.z = 1.f / (1.f + acc.z);
        ev.w = 1.f / (1.f + acc.w);
        *(float4*)&g_ev[b][k0 + t * 4] = ev;
    }
}

// ---------------- consume: exact fp32 recompute of E; row sums, perm @ ref_xyz, perm write ----------------
__global__ void __launch_bounds__(256) k_consume(const int* nreg, int r,
                                                 const float* __restrict__ beta_, const float* __restrict__ alpha_,
                                                 float* __restrict__ perm_out)
{
    int nr = dval(nreg, 3);
    if (r >= nr) return;
    bool last = (r == nr - 1);
    int b = blockIdx.y;
    __shared__ float gs[6][NPT];
    __shared__ float pk[NPT];
    __shared__ float evs[NPT];
    float bl = beta_[b] * L2E;
    for (int i = threadIdx.x; i < NPT; i += 256) {
#pragma unroll
        for (int c = 0; c < 6; c++) gs[c][i] = g_refSoA[b][c][i];
        pk[i] = bl * g_gn[b][i];
        evs[i] = g_ev[b][i];
    }
    __syncthreads();
    int warp = threadIdx.x >> 5, lane = threadIdx.x & 31;
    int j0 = blockIdx.x * 32 + warp * 4;
    float al = alpha_[b];
    float wj[4][6], cj[4], eu[4];
#pragma unroll
    for (int t = 0; t < 4; t++) {
        int j = j0 + t;
#pragma unroll
        for (int c = 0; c < 6; c++) wj[t][c] = 2.f * bl * g_featS[b][c][j];
        cj[t] = bl * (al - g_fn[b][j]);
        eu[t] = g_eu[b][j];
    }
    float S[4] = {0,0,0,0}, SX[4] = {0,0,0,0}, SY[4] = {0,0,0,0}, SZ[4] = {0,0,0,0};
    if (last) {
        float* pb[4];
#pragma unroll
        for (int t = 0; t < 4; t++) pb[t] = perm_out + ((size_t)(b * NPT + j0 + t)) * NPT;
#pragma unroll 2
        for (int i = 0; i < 32; i++) {
            int k = i * 32 + lane;
            float G[6];
#pragma unroll
            for (int c = 0; c < 6; c++) G[c] = gs[c][k];
            float P = pk[k], ev = evs[k];
#pragma unroll
            for (int t = 0; t < 4; t++) {
                float a = cj[t] - P;
#pragma unroll
                for (int c = 0; c < 6; c++) a = fmaf(wj[t][c], G[c], a);
                float e = fast_ex2(a) * ev;
                S[t] += e;
                SX[t] = fmaf(e, G[0], SX[t]);
                SY[t] = fmaf(e, G[1], SY[t]);
                SZ[t] = fmaf(e, G[2], SZ[t]);
                pb[t][k] = e * eu[t];
            }
        }
    } else {
#pragma unroll 2
        for (int i = 0; i < 32; i++) {
            int k = i * 32 + lane;
            float G[6];
#pragma unroll
            for (int c = 0; c < 6; c++) G[c] = gs[c][k];
            float P = pk[k], ev = evs[k];
#pragma unroll
            for (int t = 0; t < 4; t++) {
                float a = cj[t] - P;
#pragma unroll
                for (int c = 0; c < 6; c++) a = fmaf(wj[t][c], G[c], a);
                float e = fast_ex2(a) * ev;
                S[t] += e;
                SX[t] = fmaf(e, G[0], SX[t]);
                SY[t] = fmaf(e, G[1], SY[t]);
                SZ[t] = fmaf(e, G[2], SZ[t]);
            }
        }
    }
#pragma unroll
    for (int t = 0; t < 4; t++) {
#pragma unroll
        for (int o = 16; o; o >>= 1) {
            S[t]  += __shfl_xor_sync(0xffffffffu, S[t],  o);
            SX[t] += __shfl_xor_sync(0xffffffffu, SX[t], o);
            SY[t] += __shfl_xor_sync(0xffffffffu, SY[t], o);
            SZ[t] += __shfl_xor_sync(0xffffffffu, SZ[t], o);
        }
    }
    if (lane == 0) {
#pragma unroll
        for (int t = 0; t < 4; t++) {
            int j = j0 + t;
            float W = S[t] * eu[t];
            g_w[b][j] = W;
            float inv = 1.f / (W + EPSW);
            g_wrx[b][j] = SX[t] * eu[t] * inv;
            g_wry[b][j] = SY[t] * eu[t] * inv;
            g_wrz[b][j] = SZ[t] * eu[t] * inv;
        }
    }
}

// ---------------- fit: weighted Kabsch (fp64 Jacobi SVD) + compose transform ----------------
__global__ void __launch_bounds__(256) k_fit(const int* nreg, int r, float* __restrict__ T_out)
{
    int nr = dval(nreg, 3);
    if (r >= nr) return;
    int b = blockIdx.x;
    int lane = threadIdx.x & 31, warp = threadIdx.x >> 5;
    __shared__ double sred[8][9];
    __shared__ double sc[8];

    double acc[7] = {0,0,0,0,0,0,0};
    for (int j = threadIdx.x; j < NPT; j += 256) {
        double w  = g_w[b][j];
        double ax = g_featS[b][0][j], ay = g_featS[b][1][j], az = g_featS[b][2][j];
        double bx = g_wrx[b][j], by = g_wry[b][j], bz = g_wrz[b][j];
        acc[0] += w;
        acc[1] += w*ax; acc[2] += w*ay; acc[3] += w*az;
        acc[4] += w*bx; acc[5] += w*by; acc[6] += w*bz;
    }
#pragma unroll
    for (int i = 0; i < 7; i++)
#pragma unroll
        for (int o = 16; o; o >>= 1) acc[i] += __shfl_xor_sync(0xffffffffu, acc[i], o);
    if (lane == 0)
#pragma unroll
        for (int i = 0; i < 7; i++) sred[warp][i] = acc[i];
    __syncthreads();
    if (threadIdx.x == 0) {
        double tot[7] = {0,0,0,0,0,0,0};
        for (int w = 0; w < 8; w++)
            for (int i = 0; i < 7; i++) tot[i] += sred[w][i];
        double den = tot[0] + 1e-5;
        sc[0] = den;
        for (int i = 0; i < 6; i++) sc[1 + i] = tot[1 + i] / den;
    }
    __syncthreads();
    double den = sc[0];
    double ca0 = sc[1], ca1 = sc[2], ca2 = sc[3];
    double cb0 = sc[4], cb1 = sc[5], cb2 = sc[6];

    double cv[9] = {0,0,0,0,0,0,0,0,0};
    for (int j = threadIdx.x; j < NPT; j += 256) {
        double wn = (double)g_w[b][j] / den;
        double ax = g_featS[b][0][j] - ca0, ay = g_featS[b][1][j] - ca1, az = g_featS[b][2][j] - ca2;
        double bx = g_wrx[b][j] - cb0, by = g_wry[b][j] - cb1, bz = g_wrz[b][j] - cb2;
        cv[0] += wn*ax*bx; cv[1] += wn*ax*by; cv[2] += wn*ax*bz;
        cv[3] += wn*ay*bx; cv[4] += wn*ay*by; cv[5] += wn*ay*bz;
        cv[6] += wn*az*bx; cv[7] += wn*az*by; cv[8] += wn*az*bz;
    }
#pragma unroll
    for (int i = 0; i < 9; i++)
#pragma unroll
        for (int o = 16; o; o >>= 1) cv[i] += __shfl_xor_sync(0xffffffffu, cv[i], o);
    if (lane == 0)
#pragma unroll
        for (int i = 0; i < 9; i++) sred[warp][i] = cv[i];
    __syncthreads();

    if (threadIdx.x == 0) {
        double C[3][3];
        {
            double tot[9] = {0,0,0,0,0,0,0,0,0};
            for (int w = 0; w < 8; w++)
                for (int i = 0; i < 9; i++) tot[i] += sred[w][i];
            for (int m = 0; m < 3; m++)
                for (int n = 0; n < 3; n++) C[m][n] = tot[m * 3 + n];
        }
        double A[3][3];
        for (int i = 0; i < 3; i++)
            for (int j = 0; j < 3; j++)
                A[i][j] = C[0][i]*C[0][j] + C[1][i]*C[1][j] + C[2][i]*C[2][j];
        double V[3][3] = {{1,0,0},{0,1,0},{0,0,1}};
        const int PP[3] = {0,0,1}, QQ[3] = {1,2,2};
        for (int sweep = 0; sweep < 30; sweep++) {
            double off = A[0][1]*A[0][1] + A[0][2]*A[0][2] + A[1][2]*A[1][2];
            if (off < 1e-26) break;
            for (int pi = 0; pi < 3; pi++) {
                int p = PP[pi], q = QQ[pi];
                double apq = A[p][q];
                if (fabs(apq) < 1e-300) continue;
                double theta = (A[q][q] - A[p][p]) / (2.0 * apq);
                double tt = ((theta >= 0.0) ? 1.0 : -1.0) / (fabs(theta) + sqrt(theta*theta + 1.0));
                double c = 1.0 / sqrt(tt*tt + 1.0), sn = tt * c;
                int m = 3 - p - q;
                double amp = A[m][p], amq = A[m][q];
                double app = A[p][p], aqq = A[q][q];
                A[p][p] = app - tt * apq;
                A[q][q] = aqq + tt * apq;
                A[p][q] = A[q][p] = 0.0;
                A[m][p] = A[p][m] = c*amp - sn*amq;
                A[m][q] = A[q][m] = sn*amp + c*amq;
                for (int mm = 0; mm < 3; mm++) {
                    double vp = V[mm][p], vq = V[mm][q];
                    V[mm][p] = c*vp - sn*vq;
                    V[mm][q] = sn*vp + c*vq;
                }
            }
        }
        double lam[3] = {A[0][0], A[1][1], A[2][2]};
        for (int i = 0; i < 2; i++)
            for (int j = i + 1; j < 3; j++)
                if (lam[j] > lam[i]) {
                    double tl = lam[i]; lam[i] = lam[j]; lam[j] = tl;
                    for (int m = 0; m < 3; m++) { double tv = V[m][i]; V[m][i] = V[m][j]; V[m][j] = tv; }
                }
        double v0[3] = {V[0][0], V[1][0], V[2][0]};
        double v1[3] = {V[0][1], V[1][1], V[2][1]};
        double v2[3] = {V[0][2], V[1][2], V[2][2]};
        double u0[3], u1[3], u2[3];
        for (int m = 0; m < 3; m++) {
            u0[m] = C[m][0]*v0[0] + C[m][1]*v0[1] + C[m][2]*v0[2];
            u1[m] = C[m][0]*v1[0] + C[m][1]*v1[1] + C[m][2]*v1[2];
            u2[m] = C[m][0]*v2[0] + C[m][1]*v2[1] + C[m][2]*v2[2];
        }
        double n0 = sqrt(u0[0]*u0[0] + u0[1]*u0[1] + u0[2]*u0[2]);
        if (n0 > 1e-150) { u0[0] /= n0; u0[1] /= n0; u0[2] /= n0; }
        else { u0[0] = 1; u0[1] = 0; u0[2] = 0; n0 = 0; }
        double d01 = u0[0]*u1[0] + u0[1]*u1[1] + u0[2]*u1[2];
        for (int m = 0; m < 3; m++) u1[m] -= d01 * u0[m];
        double n1 = sqrt(u1[0]*u1[0] + u1[1]*u1[1] + u1[2]*u1[2]);
        if (n1 > 1e-150) { u1[0] /= n1; u1[1] /= n1; u1[2] /= n1; }
        else {
            double e[3] = {0,0,0};
            e[(fabs(u0[0]) < 0.9) ? 0 : 1] = 1.0;
            double de = u0[0]*e[0] + u0[1]*e[1] + u0[2]*e[2];
            for (int m = 0; m < 3; m++) u1[m] = e[m] - de * u0[m];
            double nn = sqrt(u1[0]*u1[0] + u1[1]*u1[1] + u1[2]*u1[2]);
            for (int m = 0; m < 3; m++) u1[m] /= nn;
        }
        double d02 = u0[0]*u2[0] + u0[1]*u2[1] + u0[2]*u2[2];
        double d12 = u1[0]*u2[0] + u1[1]*u2[1] + u1[2]*u2[2];
        for (int m = 0; m < 3; m++) u2[m] -= d02 * u0[m] + d12 * u1[m];
        double n2 = sqrt(u2[0]*u2[0] + u2[1]*u2[1] + u2[2]*u2[2]);
        if (n2 > 1e-12 * (n0 + 1e-300)) { u2[0] /= n2; u2[1] /= n2; u2[2] /= n2; }
        else {
            u2[0] = u0[1]*u1[2] - u0[2]*u1[1];
            u2[1] = u0[2]*u1[0] - u0[0]*u1[2];
            u2[2] = u0[0]*u1[1] - u0[1]*u1[0];
        }
        double cx0 = u1[1]*u2[2] - u1[2]*u2[1];
        double cx1 = u1[2]*u2[0] - u1[0]*u2[2];
        double cx2 = u1[0]*u2[1] - u1[1]*u2[0];
        double detU = u0[0]*cx0 + u0[1]*cx1 + u0[2]*cx2;
        double cy0 = v1[1]*v2[2] - v1[2]*v2[1];
        double cy1 = v1[2]*v2[0] - v1[0]*v2[2];
        double cy2 = v1[0]*v2[1] - v1[1]*v2[0];
        double detV = v0[0]*cy0 + v0[1]*cy1 + v0[2]*cy2;
        double dd = (detU * detV >= 0.0) ? 1.0 : -1.0;
        double R[3][3];
        for (int m = 0; m < 3; m++)
            for (int n = 0; n < 3; n++)
                R[m][n] = v0[m]*u0[n] + v1[m]*u1[n] + dd * v2[m]*u2[n];
        double t3[3];
        t3[0] = cb0 - (R[0][0]*ca0 + R[0][1]*ca1 + R[0][2]*ca2);
        t3[1] = cb1 - (R[1][0]*ca0 + R[1][1]*ca1 + R[1][2]*ca2);
        t3[2] = cb2 - (R[2][0]*ca0 + R[2][1]*ca1 + R[2][2]*ca2);
        double* To = g_T[b];
        double Rn[9], tn[3];
        for (int m = 0; m < 3; m++) {
            for (int n = 0; n < 3; n++)
                Rn[m*3+n] = R[m][0]*To[0*4+n] + R[m][1]*To[1*4+n] + R[m][2]*To[2*4+n];
            tn[m] = R[m][0]*To[3] + R[m][1]*To[7] + R[m][2]*To[11] + t3[m];
        }
        for (int m = 0; m < 3; m++) {
            for (int n = 0; n < 3; n++) To[m*4+n] = Rn[m*3+n];
            To[m*4+3] = tn[m];
        }
        if (r == nr - 1 && T_out) {
            for (int m = 0; m < 3; m++)
                for (int n = 0; n < 4; n++)
                    T_out[b * 12 + m * 4 + n] = (float)To[m * 4 + n];
        }
    }
}

// ---------------- launch ----------------
extern "C" void kernel_launch(void* const* d_in, const int* in_sizes, int n_in,
                              void* d_out, int out_size)
{
    const float* src   = (const float*)d_in[0];
    const float* ref   = (const float*)d_in[1];
    const float* beta  = (const float*)d_in[2];
    const float* alpha = (const float*)d_in[3];
    const int*   nreg  = (n_in > 4) ? (const int*)d_in[4] : nullptr;
    const int*   nsk   = (n_in > 5) ? (const int*)d_in[5] : nullptr;

    float* out = (float*)d_out;
    const long permN = (long)BB * NPT * NPT;
    long off = (long)out_size - permN;
    if (off < 0) off = 0;
    float* perm_out = out + off;
    float* T_out = (off >= BB * 12) ? out : nullptr;

    k_init<<<64, 256>>>(ref);
    const int RMAX = 3, SMAX = 5;
    dim3 gridMat(NPT / 32, BB);       // 512 blocks
    dim3 gridSink(SINK_JC, BB);       // 512 blocks
    dim3 gridFold(NPT / 128, BB);     // 128 blocks
    for (int r = 0; r < RMAX; r++) {
        k_prep<<<64, 256>>>(nreg, r, src);
        k_mat<<<gridMat, 256>>>(nreg, r, beta, alpha);     // fp16 E + eu1 (row pass, ev==1)
        for (int s = 0; s < SMAX; s++) {
            k_sink<<<gridSink, 256>>>(nreg, nsk, r, s);    // one TMA sweep: eu update + col partials
            k_fold<<<gridFold, 256>>>(nreg, nsk, r, s);    // partials -> g_ev
        }
        k_consume<<<gridMat, 256>>>(nreg, r, beta, alpha, perm_out);
        k_fit<<<BB, 256>>>(nreg, r, T_out);
    }
}

// round 14
// speedup vs baseline: 1.1032x; 1.0759x over previous
#include <cuda_runtime.h>
#include <cuda_fp16.h>
#include <math.h>

#define BB  16
#define NPT 1024
#define EPSW 1e-5f
#define L2E 1.4426950408889634f

typedef unsigned long long ull;

// ---------------- scratch (static device globals; no allocations) ----------------
static __device__ __half g_Eh[BB][NPT][NPT];     // exp(affinity) fp16, 32MB
static __device__ float  g_part[4][BB][NPT];     // column-pass partial sums (4 j-chunks)
static __device__ float  g_refSoA[BB][6][NPT];
static __device__ float  g_gn[BB][NPT];
static __device__ float  g_featS[BB][6][NPT];
static __device__ float  g_fn[BB][NPT];
static __device__ float  g_eu[BB][NPT];          // exp(-u_j)
static __device__ float  g_w[BB][NPT];
static __device__ float  g_wrx[BB][NPT];
static __device__ float  g_wry[BB][NPT];
static __device__ float  g_wrz[BB][NPT];
static __device__ double g_T[BB][12];

__device__ __forceinline__ float fast_ex2(float x){ float y; asm("ex2.approx.ftz.f32 %0, %1;" : "=f"(y) : "f"(x)); return y; }
__device__ __forceinline__ int dval(const int* p, int d){ return p ? __ldg(p) : d; }

// packed f32x2 helpers (Blackwell FFMA2)
__device__ __forceinline__ ull pack2(float lo, float hi){ ull r; asm("mov.b64 %0, {%1, %2};" : "=l"(r) : "f"(lo), "f"(hi)); return r; }
__device__ __forceinline__ void unpack2(ull v, float& lo, float& hi){ asm("mov.b64 {%0, %1}, %2;" : "=f"(lo), "=f"(hi) : "l"(v)); }
__device__ __forceinline__ ull fma2(ull a, ull b, ull c){ ull d; asm("fma.rn.f32x2 %0, %1, %2, %3;" : "=l"(d) : "l"(a), "l"(b), "l"(c)); return d; }
__device__ __forceinline__ ull add2(ull a, ull b){ ull d; asm("add.rn.f32x2 %0, %1, %2;" : "=l"(d) : "l"(a), "l"(b)); return d; }

// ---------------- init ----------------
__global__ void k_init(const float* __restrict__ ref)
{
    int idx = blockIdx.x * 256 + threadIdx.x;
    if (idx < BB * NPT) {
        int b = idx >> 10, k = idx & 1023;
        const float* p = ref + (size_t)idx * 6;
        float n = 0.f;
#pragma unroll
        for (int c = 0; c < 6; c++) { float x = p[c]; g_refSoA[b][c][k] = x; n += x * x; }
        g_gn[b][k] = n;
    }
    if (idx < BB) {
        double* T = g_T[idx];
#pragma unroll
        for (int m = 0; m < 3; m++)
#pragma unroll
            for (int c = 0; c < 4; c++) T[m * 4 + c] = (m == c) ? 1.0 : 0.0;
    }
}

// ---------------- prep: transform src + zero col partials (for matp atomics) ----------------
__global__ void k_prep(const int* nreg, int r, const float* __restrict__ src)
{
    if (r >= dval(nreg, 3)) return;
    int idx = blockIdx.x * 256 + threadIdx.x;
    // zero g_part: 4*BB*NPT = 65536 floats over 16384 threads
    float* gp = (float*)g_part;
#pragma unroll
    for (int i = 0; i < 4; i++) gp[idx + i * 16384] = 0.f;
    if (idx >= BB * NPT) return;
    int b = idx >> 10, j = idx & 1023;
    const double* T = g_T[b];
    const float* p = src + (size_t)idx * 6;
    float x = p[0], y = p[1], z = p[2], n3 = p[3], n4 = p[4], n5 = p[5];
    float q0 = (float)(T[0] * x + T[1] * y + T[2]  * z + T[3]);
    float q1 = (float)(T[4] * x + T[5] * y + T[6]  * z + T[7]);
    float q2 = (float)(T[8] * x + T[9] * y + T[10] * z + T[11]);
    g_featS[b][0][j] = q0; g_featS[b][1][j] = q1; g_featS[b][2][j] = q2;
    g_featS[b][3][j] = n3; g_featS[b][4][j] = n4; g_featS[b][5][j] = n5;
    g_fn[b][j] = q0*q0 + q1*q1 + q2*q2 + n3*n3 + n4*n4 + n5*n5;
}

// ---------------- matp: E = exp(a) (fp16) + eu1 + FUSED s=0 col partials (tile kept in smem) ----------------
// dynamic smem: gs 24KB | pk 4KB | Et 64KB | eusS 128B  (94336 B total)
__global__ void __launch_bounds__(256) k_matp(const int* nreg, int r,
                                              const float* __restrict__ beta_, const float* __restrict__ alpha_)
{
    if (r >= dval(nreg, 3)) return;
    extern __shared__ char dyn[];
    float (*gs)[NPT] = (float(*)[NPT])dyn;                          // 6*4KB
    float* pk        = (float*)(dyn + 24 * 1024);                   // 4KB
    __half2 (*Et)[NPT / 2] = (__half2(*)[NPT / 2])(dyn + 28 * 1024); // 32 rows * 2KB
    float* eusS      = (float*)(dyn + 92 * 1024);                   // 32 floats

    int b = blockIdx.y;
    float bl = beta_[b] * L2E;
    for (int i = threadIdx.x; i < NPT; i += 256) {
#pragma unroll
        for (int c = 0; c < 6; c++) gs[c][i] = g_refSoA[b][c][i];
        pk[i] = bl * g_gn[b][i];
    }
    __syncthreads();
    int warp = threadIdx.x >> 5, lane = threadIdx.x & 31;
    int jc = blockIdx.x;                 // 0..31
    int j0 = jc * 32 + warp * 4;
    float al = alpha_[b];
    ull wj2[4][6], cj2[4];
#pragma unroll
    for (int t = 0; t < 4; t++) {
        int j = j0 + t;
#pragma unroll
        for (int c = 0; c < 6; c++) { float w = 2.f * bl * g_featS[b][c][j]; wj2[t][c] = pack2(w, w); }
        float cj = bl * (al - g_fn[b][j]);
        cj2[t] = pack2(cj, cj);
    }
    __half2* E0 = (__half2*)&g_Eh[b][j0][0];
    float acc[4] = {0.f, 0.f, 0.f, 0.f};
#pragma unroll 2
    for (int i = 0; i < 16; i++) {
        int kk = i * 32 + lane;
        ull g2[6];
#pragma unroll
        for (int c = 0; c < 6; c++) {
            float2 G = ((const float2*)&gs[c][0])[kk];
            g2[c] = pack2(G.x, G.y);
        }
        float2 P = ((const float2*)pk)[kk];
        ull pn = pack2(-P.x, -P.y);
#pragma unroll
        for (int t = 0; t < 4; t++) {
            ull a = add2(cj2[t], pn);
#pragma unroll
            for (int c = 0; c < 6; c++) a = fma2(wj2[t][c], g2[c], a);
            float ax, ay; unpack2(a, ax, ay);
            float e0 = fast_ex2(ax), e1 = fast_ex2(ay);
            __half2 h = __floats2half2_rn(e0, e1);
            E0[t * (NPT / 2) + kk] = h;
            Et[warp * 4 + t][kk] = h;
            acc[t] += e0 + e1;
        }
    }
#pragma unroll
    for (int t = 0; t < 4; t++)
#pragma unroll
        for (int o = 16; o; o >>= 1) acc[t] += __shfl_xor_sync(0xffffffffu, acc[t], o);
    if (lane == 0) {
#pragma unroll
        for (int t = 0; t < 4; t++) {
            float eu = 1.f / (1.f + acc[t]);
            g_eu[b][j0 + t] = eu;
            eusS[warp * 4 + t] = eu;
        }
    }
    __syncthreads();
    // col phase: thread t -> columns 4t..4t+3, sum over this block's 32 rows
    int t = threadIdx.x;
    float a0 = 0.f, a1 = 0.f, a2 = 0.f, a3 = 0.f;
#pragma unroll 8
    for (int q = 0; q < 32; q++) {
        uint2 hv = ((const uint2*)&Et[q][0])[t];
        float e = eusS[q];
        float2 q0 = __half22float2(*(const __half2*)&hv.x);
        float2 q1 = __half22float2(*(const __half2*)&hv.y);
        a0 = fmaf(q0.x, e, a0);
        a1 = fmaf(q0.y, e, a1);
        a2 = fmaf(q1.x, e, a2);
        a3 = fmaf(q1.y, e, a3);
    }
    int jc4 = jc >> 3;          // 8 writer-blocks per slot
    float* dst = &g_part[jc4][b][t * 4];
    atomicAdd(dst + 0, a0);
    atomicAdd(dst + 1, a1);
    atomicAdd(dst + 2, a2);
    atomicAdd(dst + 3, a3);
}

// ---------------- col pass (partial): part[jc][b][k] = sum_{j in chunk} E_jk * eu_j ----------------
// grid (32, BB): kc = x&7 (8 chunks of 128 cols), jc = x>>3 (4 chunks of 256 rows)
__global__ void __launch_bounds__(256) k_colp(const int* nreg, const int* nsk, int r, int s)
{
    if (r >= dval(nreg, 3) || s >= dval(nsk, 5)) return;
    int b  = blockIdx.y;
    int kc = blockIdx.x & 7;
    int jc = blockIdx.x >> 3;
    int t = threadIdx.x;
    int col8 = t & 15;          // 16 groups of 8 columns
    int rg   = t >> 4;          // 16 row-chunks of 16 rows
    __shared__ float eus[256];
    __shared__ float red[16][128];
    eus[t] = g_eu[b][jc * 256 + t];
    __syncthreads();
    const uint4* Ebase = (const uint4*)(&g_Eh[b][jc * 256 + rg * 16][kc * 128 + col8 * 8]);
    const int rowStride = NPT / 8;   // uint4 elements per row
    float a0=0,a1=0,a2=0,a3=0,a4=0,a5=0,a6=0,a7=0;
#pragma unroll
    for (int jj = 0; jj < 16; jj++) {
        uint4 v = Ebase[jj * rowStride];
        float e = eus[rg * 16 + jj];
        float2 p0 = __half22float2(*(const __half2*)&v.x);
        float2 p1 = __half22float2(*(const __half2*)&v.y);
        float2 p2 = __half22float2(*(const __half2*)&v.z);
        float2 p3 = __half22float2(*(const __half2*)&v.w);
        a0 = fmaf(p0.x, e, a0); a1 = fmaf(p0.y, e, a1);
        a2 = fmaf(p1.x, e, a2); a3 = fmaf(p1.y, e, a3);
        a4 = fmaf(p2.x, e, a4); a5 = fmaf(p2.y, e, a5);
        a6 = fmaf(p3.x, e, a6); a7 = fmaf(p3.y, e, a7);
    }
    red[rg][0*16 + col8] = a0; red[rg][1*16 + col8] = a1;
    red[rg][2*16 + col8] = a2; red[rg][3*16 + col8] = a3;
    red[rg][4*16 + col8] = a4; red[rg][5*16 + col8] = a5;
    red[rg][6*16 + col8] = a6; red[rg][7*16 + col8] = a7;
    __syncthreads();
    if (t < 128) {
        int c8 = t >> 3, ci = t & 7;       // column c = c8*8 + ci
        float s4 = 0.f;
#pragma unroll
        for (int rr = 0; rr < 16; rr++) s4 += red[rr][ci * 16 + c8];
        g_part[jc][b][kc * 128 + c8 * 8 + ci] = s4;
    }
}

// ---------------- row pass: eu_j = 1/(1 + sum_k E_jk * ev_k), ev from partials ----------------
// grid (32, BB): 8 warps/block, 4 rows/warp
__global__ void __launch_bounds__(256) k_rowp(const int* nreg, const int* nsk, int r, int s)
{
    if (r >= dval(nreg, 3) || s >= dval(nsk, 5)) return;
    int b = blockIdx.y;
    __shared__ float evs[NPT];
    for (int i = threadIdx.x; i < NPT; i += 256)
        evs[i] = 1.f / (1.f + g_part[0][b][i] + g_part[1][b][i] + g_part[2][b][i] + g_part[3][b][i]);
    __syncthreads();
    int w = threadIdx.x >> 5, lane = threadIdx.x & 31;
    int j0 = (blockIdx.x * 8 + w) * 4;
    float acc0 = 0.f, acc1 = 0.f, acc2 = 0.f, acc3 = 0.f;
#pragma unroll
    for (int i = 0; i < 4; i++) {
        int k0 = i * 256 + lane * 8;
        float2 e0 = *(const float2*)&evs[k0];
        float2 e1 = *(const float2*)&evs[k0 + 2];
        float2 e2 = *(const float2*)&evs[k0 + 4];
        float2 e3 = *(const float2*)&evs[k0 + 6];
        uint4 v0 = *(const uint4*)(&g_Eh[b][j0 + 0][k0]);
        uint4 v1 = *(const uint4*)(&g_Eh[b][j0 + 1][k0]);
        uint4 v2 = *(const uint4*)(&g_Eh[b][j0 + 2][k0]);
        uint4 v3 = *(const uint4*)(&g_Eh[b][j0 + 3][k0]);
        {
            float2 p0 = __half22float2(*(const __half2*)&v0.x), p1 = __half22float2(*(const __half2*)&v0.y);
            float2 p2 = __half22float2(*(const __half2*)&v0.z), p3 = __half22float2(*(const __half2*)&v0.w);
            acc0 = fmaf(p0.x, e0.x, fmaf(p0.y, e0.y, acc0));
            acc0 = fmaf(p1.x, e1.x, fmaf(p1.y, e1.y, acc0));
            acc0 = fmaf(p2.x, e2.x, fmaf(p2.y, e2.y, acc0));
            acc0 = fmaf(p3.x, e3.x, fmaf(p3.y, e3.y, acc0));
        }
        {
            float2 p0 = __half22float2(*(const __half2*)&v1.x), p1 = __half22float2(*(const __half2*)&v1.y);
            float2 p2 = __half22float2(*(const __half2*)&v1.z), p3 = __half22float2(*(const __half2*)&v1.w);
            acc1 = fmaf(p0.x, e0.x, fmaf(p0.y, e0.y, acc1));
            acc1 = fmaf(p1.x, e1.x, fmaf(p1.y, e1.y, acc1));
            acc1 = fmaf(p2.x, e2.x, fmaf(p2.y, e2.y, acc1));
            acc1 = fmaf(p3.x, e3.x, fmaf(p3.y, e3.y, acc1));
        }
        {
            float2 p0 = __half22float2(*(const __half2*)&v2.x), p1 = __half22float2(*(const __half2*)&v2.y);
            float2 p2 = __half22float2(*(const __half2*)&v2.z), p3 = __half22float2(*(const __half2*)&v2.w);
            acc2 = fmaf(p0.x, e0.x, fmaf(p0.y, e0.y, acc2));
            acc2 = fmaf(p1.x, e1.x, fmaf(p1.y, e1.y, acc2));
            acc2 = fmaf(p2.x, e2.x, fmaf(p2.y, e2.y, acc2));
            acc2 = fmaf(p3.x, e3.x, fmaf(p3.y, e3.y, acc2));
        }
        {
            float2 p0 = __half22float2(*(const __half2*)&v3.x), p1 = __half22float2(*(const __half2*)&v3.y);
            float2 p2 = __half22float2(*(const __half2*)&v3.z), p3 = __half22float2(*(const __half2*)&v3.w);
            acc3 = fmaf(p0.x, e0.x, fmaf(p0.y, e0.y, acc3));
            acc3 = fmaf(p1.x, e1.x, fmaf(p1.y, e1.y, acc3));
            acc3 = fmaf(p2.x, e2.x, fmaf(p2.y, e2.y, acc3));
            acc3 = fmaf(p3.x, e3.x, fmaf(p3.y, e3.y, acc3));
        }
    }
#pragma unroll
    for (int o = 16; o; o >>= 1) {
        acc0 += __shfl_xor_sync(0xffffffffu, acc0, o);
        acc1 += __shfl_xor_sync(0xffffffffu, acc1, o);
        acc2 += __shfl_xor_sync(0xffffffffu, acc2, o);
        acc3 += __shfl_xor_sync(0xffffffffu, acc3, o);
    }
    if (lane == 0) {
        g_eu[b][j0 + 0] = 1.f / (1.f + acc0);
        g_eu[b][j0 + 1] = 1.f / (1.f + acc1);
        g_eu[b][j0 + 2] = 1.f / (1.f + acc2);
        g_eu[b][j0 + 3] = 1.f / (1.f + acc3);
    }
}

// ---------------- consume: exact fp32 recompute of E; row sums, perm @ ref_xyz, perm write ----------------
__global__ void __launch_bounds__(256) k_consume(const int* nreg, int r,
                                                 const float* __restrict__ beta_, const float* __restrict__ alpha_,
                                                 float* __restrict__ perm_out)
{
    int nr = dval(nreg, 3);
    if (r >= nr) return;
    bool last = (r == nr - 1);
    int b = blockIdx.y;
    __shared__ float gs[6][NPT];
    __shared__ float pk[NPT];
    __shared__ float evs[NPT];
    float bl = beta_[b] * L2E;
    for (int i = threadIdx.x; i < NPT; i += 256) {
#pragma unroll
        for (int c = 0; c < 6; c++) gs[c][i] = g_refSoA[b][c][i];
        pk[i] = bl * g_gn[b][i];
        evs[i] = 1.f / (1.f + g_part[0][b][i] + g_part[1][b][i] + g_part[2][b][i] + g_part[3][b][i]);
    }
    __syncthreads();
    int warp = threadIdx.x >> 5, lane = threadIdx.x & 31;
    int j0 = blockIdx.x * 32 + warp * 4;
    float al = alpha_[b];
    float wj[4][6], cj[4], eu[4];
#pragma unroll
    for (int t = 0; t < 4; t++) {
        int j = j0 + t;
#pragma unroll
        for (int c = 0; c < 6; c++) wj[t][c] = 2.f * bl * g_featS[b][c][j];
        cj[t] = bl * (al - g_fn[b][j]);
        eu[t] = g_eu[b][j];
    }
    float S[4] = {0,0,0,0}, SX[4] = {0,0,0,0}, SY[4] = {0,0,0,0}, SZ[4] = {0,0,0,0};
    if (last) {
        float* pb[4];
#pragma unroll
        for (int t = 0; t < 4; t++) pb[t] = perm_out + ((size_t)(b * NPT + j0 + t)) * NPT;
#pragma unroll 2
        for (int i = 0; i < 32; i++) {
            int k = i * 32 + lane;
            float G[6];
#pragma unroll
            for (int c = 0; c < 6; c++) G[c] = gs[c][k];
            float P = pk[k], ev = evs[k];
#pragma unroll
            for (int t = 0; t < 4; t++) {
                float a = cj[t] - P;
#pragma unroll
                for (int c = 0; c < 6; c++) a = fmaf(wj[t][c], G[c], a);
                float e = fast_ex2(a) * ev;
                S[t] += e;
                SX[t] = fmaf(e, G[0], SX[t]);
                SY[t] = fmaf(e, G[1], SY[t]);
                SZ[t] = fmaf(e, G[2], SZ[t]);
                pb[t][k] = e * eu[t];
            }
        }
    } else {
#pragma unroll 2
        for (int i = 0; i < 32; i++) {
            int k = i * 32 + lane;
            float G[6];
#pragma unroll
            for (int c = 0; c < 6; c++) G[c] = gs[c][k];
            float P = pk[k], ev = evs[k];
#pragma unroll
            for (int t = 0; t < 4; t++) {
                float a = cj[t] - P;
#pragma unroll
                for (int c = 0; c < 6; c++) a = fmaf(wj[t][c], G[c], a);
                float e = fast_ex2(a) * ev;
                S[t] += e;
                SX[t] = fmaf(e, G[0], SX[t]);
                SY[t] = fmaf(e, G[1], SY[t]);
                SZ[t] = fmaf(e, G[2], SZ[t]);
            }
        }
    }
#pragma unroll
    for (int t = 0; t < 4; t++) {
#pragma unroll
        for (int o = 16; o; o >>= 1) {
            S[t]  += __shfl_xor_sync(0xffffffffu, S[t],  o);
            SX[t] += __shfl_xor_sync(0xffffffffu, SX[t], o);
            SY[t] += __shfl_xor_sync(0xffffffffu, SY[t], o);
            SZ[t] += __shfl_xor_sync(0xffffffffu, SZ[t], o);
        }
    }
    if (lane == 0) {
#pragma unroll
        for (int t = 0; t < 4; t++) {
            int j = j0 + t;
            float W = S[t] * eu[t];
            g_w[b][j] = W;
            float inv = 1.f / (W + EPSW);
            g_wrx[b][j] = SX[t] * eu[t] * inv;
            g_wry[b][j] = SY[t] * eu[t] * inv;
            g_wrz[b][j] = SZ[t] * eu[t] * inv;
        }
    }
}

// ---------------- fit: weighted Kabsch (fp64 Jacobi SVD) + compose transform ----------------
__global__ void __launch_bounds__(256) k_fit(const int* nreg, int r, float* __restrict__ T_out)
{
    int nr = dval(nreg, 3);
    if (r >= nr) return;
    int b = blockIdx.x;
    int lane = threadIdx.x & 31, warp = threadIdx.x >> 5;
    __shared__ double sred[8][9];
    __shared__ double sc[8];

    double acc[7] = {0,0,0,0,0,0,0};
    for (int j = threadIdx.x; j < NPT; j += 256) {
        double w  = g_w[b][j];
        double ax = g_featS[b][0][j], ay = g_featS[b][1][j], az = g_featS[b][2][j];
        double bx = g_wrx[b][j], by = g_wry[b][j], bz = g_wrz[b][j];
        acc[0] += w;
        acc[1] += w*ax; acc[2] += w*ay; acc[3] += w*az;
        acc[4] += w*bx; acc[5] += w*by; acc[6] += w*bz;
    }
#pragma unroll
    for (int i = 0; i < 7; i++)
#pragma unroll
        for (int o = 16; o; o >>= 1) acc[i] += __shfl_xor_sync(0xffffffffu, acc[i], o);
    if (lane == 0)
#pragma unroll
        for (int i = 0; i < 7; i++) sred[warp][i] = acc[i];
    __syncthreads();
    if (threadIdx.x == 0) {
        double tot[7] = {0,0,0,0,0,0,0};
        for (int w = 0; w < 8; w++)
            for (int i = 0; i < 7; i++) tot[i] += sred[w][i];
        double den = tot[0] + 1e-5;
        sc[0] = den;
        for (int i = 0; i < 6; i++) sc[1 + i] = tot[1 + i] / den;
    }
    __syncthreads();
    double den = sc[0];
    double ca0 = sc[1], ca1 = sc[2], ca2 = sc[3];
    double cb0 = sc[4], cb1 = sc[5], cb2 = sc[6];

    double cv[9] = {0,0,0,0,0,0,0,0,0};
    for (int j = threadIdx.x; j < NPT; j += 256) {
        double wn = (double)g_w[b][j] / den;
        double ax = g_featS[b][0][j] - ca0, ay = g_featS[b][1][j] - ca1, az = g_featS[b][2][j] - ca2;
        double bx = g_wrx[b][j] - cb0, by = g_wry[b][j] - cb1, bz = g_wrz[b][j] - cb2;
        cv[0] += wn*ax*bx; cv[1] += wn*ax*by; cv[2] += wn*ax*bz;
        cv[3] += wn*ay*bx; cv[4] += wn*ay*by; cv[5] += wn*ay*bz;
        cv[6] += wn*az*bx; cv[7] += wn*az*by; cv[8] += wn*az*bz;
    }
#pragma unroll
    for (int i = 0; i < 9; i++)
#pragma unroll
        for (int o = 16; o; o >>= 1) cv[i] += __shfl_xor_sync(0xffffffffu, cv[i], o);
    if (lane == 0)
#pragma unroll
        for (int i = 0; i < 9; i++) sred[warp][i] = cv[i];
    __syncthreads();

    if (threadIdx.x == 0) {
        double C[3][3];
        {
            double tot[9] = {0,0,0,0,0,0,0,0,0};
            for (int w = 0; w < 8; w++)
                for (int i = 0; i < 9; i++) tot[i] += sred[w][i];
            for (int m = 0; m < 3; m++)
                for (int n = 0; n < 3; n++) C[m][n] = tot[m * 3 + n];
        }
        double A[3][3];
        for (int i = 0; i < 3; i++)
            for (int j = 0; j < 3; j++)
                A[i][j] = C[0][i]*C[0][j] + C[1][i]*C[1][j] + C[2][i]*C[2][j];
        double V[3][3] = {{1,0,0},{0,1,0},{0,0,1}};
        const int PP[3] = {0,0,1}, QQ[3] = {1,2,2};
        for (int sweep = 0; sweep < 30; sweep++) {
            double off = A[0][1]*A[0][1] + A[0][2]*A[0][2] + A[1][2]*A[1][2];
            if (off < 1e-26) break;
            for (int pi = 0; pi < 3; pi++) {
                int p = PP[pi], q = QQ[pi];
                double apq = A[p][q];
                if (fabs(apq) < 1e-300) continue;
                double theta = (A[q][q] - A[p][p]) / (2.0 * apq);
                double tt = ((theta >= 0.0) ? 1.0 : -1.0) / (fabs(theta) + sqrt(theta*theta + 1.0));
                double c = 1.0 / sqrt(tt*tt + 1.0), sn = tt * c;
                int m = 3 - p - q;
                double amp = A[m][p], amq = A[m][q];
                double app = A[p][p], aqq = A[q][q];
                A[p][p] = app - tt * apq;
                A[q][q] = aqq + tt * apq;
                A[p][q] = A[q][p] = 0.0;
                A[m][p] = A[p][m] = c*amp - sn*amq;
                A[m][q] = A[q][m] = sn*amp + c*amq;
                for (int mm = 0; mm < 3; mm++) {
                    double vp = V[mm][p], vq = V[mm][q];
                    V[mm][p] = c*vp - sn*vq;
                    V[mm][q] = sn*vp + c*vq;
                }
            }
        }
        double lam[3] = {A[0][0], A[1][1], A[2][2]};
        for (int i = 0; i < 2; i++)
            for (int j = i + 1; j < 3; j++)
                if (lam[j] > lam[i]) {
                    double tl = lam[i]; lam[i] = lam[j]; lam[j] = tl;
                    for (int m = 0; m < 3; m++) { double tv = V[m][i]; V[m][i] = V[m][j]; V[m][j] = tv; }
                }
        double v0[3] = {V[0][0], V[1][0], V[2][0]};
        double v1[3] = {V[0][1], V[1][1], V[2][1]};
        double v2[3] = {V[0][2], V[1][2], V[2][2]};
        double u0[3], u1[3], u2[3];
        for (int m = 0; m < 3; m++) {
            u0[m] = C[m][0]*v0[0] + C[m][1]*v0[1] + C[m][2]*v0[2];
            u1[m] = C[m][0]*v1[0] + C[m][1]*v1[1] + C[m][2]*v1[2];
            u2[m] = C[m][0]*v2[0] + C[m][1]*v2[1] + C[m][2]*v2[2];
        }
        double n0 = sqrt(u0[0]*u0[0] + u0[1]*u0[1] + u0[2]*u0[2]);
        if (n0 > 1e-150) { u0[0] /= n0; u0[1] /= n0; u0[2] /= n0; }
        else { u0[0] = 1; u0[1] = 0; u0[2] = 0; n0 = 0; }
        double d01 = u0[0]*u1[0] + u0[1]*u1[1] + u0[2]*u1[2];
        for (int m = 0; m < 3; m++) u1[m] -= d01 * u0[m];
        double n1 = sqrt(u1[0]*u1[0] + u1[1]*u1[1] + u1[2]*u1[2]);
        if (n1 > 1e-150) { u1[0] /= n1; u1[1] /= n1; u1[2] /= n1; }
        else {
            double e[3] = {0,0,0};
            e[(fabs(u0[0]) < 0.9) ? 0 : 1] = 1.0;
            double de = u0[0]*e[0] + u0[1]*e[1] + u0[2]*e[2];
            for (int m = 0; m < 3; m++) u1[m] = e[m] - de * u0[m];
            double nn = sqrt(u1[0]*u1[0] + u1[1]*u1[1] + u1[2]*u1[2]);
            for (int m = 0; m < 3; m++) u1[m] /= nn;
        }
        double d02 = u0[0]*u2[0] + u0[1]*u2[1] + u0[2]*u2[2];
        double d12 = u1[0]*u2[0] + u1[1]*u2[1] + u1[2]*u2[2];
        for (int m = 0; m < 3; m++) u2[m] -= d02 * u0[m] + d12 * u1[m];
        double n2 = sqrt(u2[0]*u2[0] + u2[1]*u2[1] + u2[2]*u2[2]);
        if (n2 > 1e-12 * (n0 + 1e-300)) { u2[0] /= n2; u2[1] /= n2; u2[2] /= n2; }
        else {
            u2[0] = u0[1]*u1[2] - u0[2]*u1[1];
            u2[1] = u0[2]*u1[0] - u0[0]*u1[2];
            u2[2] = u0[0]*u1[1] - u0[1]*u1[0];
        }
        double cx0 = u1[1]*u2[2] - u1[2]*u2[1];
        double cx1 = u1[2]*u2[0] - u1[0]*u2[2];
        double cx2 = u1[0]*u2[1] - u1[1]*u2[0];
        double detU = u0[0]*cx0 + u0[1]*cx1 + u0[2]*cx2;
        double cy0 = v1[1]*v2[2] - v1[2]*v2[1];
        double cy1 = v1[2]*v2[0] - v1[0]*v2[2];
        double cy2 = v1[0]*v2[1] - v1[1]*v2[0];
        double detV = v0[0]*cy0 + v0[1]*cy1 + v0[2]*cy2;
        double dd = (detU * detV >= 0.0) ? 1.0 : -1.0;
        double R[3][3];
        for (int m = 0; m < 3; m++)
            for (int n = 0; n < 3; n++)
                R[m][n] = v0[m]*u0[n] + v1[m]*u1[n] + dd * v2[m]*u2[n];
        double t3[3];
        t3[0] = cb0 - (R[0][0]*ca0 + R[0][1]*ca1 + R[0][2]*ca2);
        t3[1] = cb1 - (R[1][0]*ca0 + R[1][1]*ca1 + R[1][2]*ca2);
        t3[2] = cb2 - (R[2][0]*ca0 + R[2][1]*ca1 + R[2][2]*ca2);
        double* To = g_T[b];
        double Rn[9], tn[3];
        for (int m = 0; m < 3; m++) {
            for (int n = 0; n < 3; n++)
                Rn[m*3+n] = R[m][0]*To[0*4+n] + R[m][1]*To[1*4+n] + R[m][2]*To[2*4+n];
            tn[m] = R[m][0]*To[3] + R[m][1]*To[7] + R[m][2]*To[11] + t3[m];
        }
        for (int m = 0; m < 3; m++) {
            for (int n = 0; n < 3; n++) To[m*4+n] = Rn[m*3+n];
            To[m*4+3] = tn[m];
        }
        if (r == nr - 1 && T_out) {
            for (int m = 0; m < 3; m++)
                for (int n = 0; n < 4; n++)
                    T_out[b * 12 + m * 4 + n] = (float)To[m * 4 + n];
        }
    }
}

// ---------------- launch ----------------
extern "C" void kernel_launch(void* const* d_in, const int* in_sizes, int n_in,
                              void* d_out, int out_size)
{
    const float* src   = (const float*)d_in[0];
    const float* ref   = (const float*)d_in[1];
    const float* beta  = (const float*)d_in[2];
    const float* alpha = (const float*)d_in[3];
    const int*   nreg  = (n_in > 4) ? (const int*)d_in[4] : nullptr;
    const int*   nsk   = (n_in > 5) ? (const int*)d_in[5] : nullptr;

    float* out = (float*)d_out;
    const long permN = (long)BB * NPT * NPT;
    long off = (long)out_size - permN;
    if (off < 0) off = 0;
    float* perm_out = out + off;
    float* T_out = (off >= BB * 12) ? out : nullptr;

    const int MATP_SMEM = 24 * 1024 + 4 * 1024 + 64 * 1024 + 128;   // 94336
    cudaFuncSetAttribute(k_matp, cudaFuncAttributeMaxDynamicSharedMemorySize, MATP_SMEM);

    k_init<<<64, 256>>>(ref);
    const int RMAX = 3, SMAX = 5;
    dim3 gridMat(NPT / 32, BB);     // 512 blocks
    dim3 gridCol(32, BB);           // 8 k-chunks x 4 j-chunks
    dim3 gridRow(32, BB);           // 8 warps x 4 rows = 32 rows/block
    for (int r = 0; r < RMAX; r++) {
        k_prep<<<64, 256>>>(nreg, r, src);
        k_matp<<<gridMat, 256, MATP_SMEM>>>(nreg, r, beta, alpha);  // E + eu1 + s=0 col partials
        for (int s = 1; s < SMAX; s++) {
            k_rowp<<<gridRow, 256>>>(nreg, nsk, r, s);
            k_colp<<<gridCol, 256>>>(nreg, nsk, r, s);
        }
        k_consume<<<gridMat, 256>>>(nreg, r, beta, alpha, perm_out);
        k_fit<<<BB, 256>>>(nreg, r, T_out);
    }
}